// round 1
// baseline (speedup 1.0000x reference)
#include <cuda_runtime.h>
#include <cuda_bf16.h>

// NMU forward: y[b,o] = prod_d ( M_hat[d,o]*x[b,d] + 1 - M_hat[d,o] )
//            = prod_d ( fma(M_hat[d,o], x[b,d]-1, 1) )
// B=16384, D=256, O=32, fp32.
//
// Strategy: compute-issue bound kernel -> use packed f32x2 FMA/MUL (sm_103a).
// Block: 256 threads = 8 warps, 32 x-rows per block (4 rows per warp).
// lane = output column o. Smem: (x-1) tile + M_hat transposed (stride-258 pad
// so per-lane 64-bit m loads are bank-conflict free).

#define NMU_D 256
#define NMU_O 32
#define NMU_BROWS 32
#define NMU_RPW 4
#define NMU_MSTRIDE 258   // floats; even -> 8B aligned rows, conflict-free LDS.64

__device__ __forceinline__ unsigned long long f2_fma(unsigned long long a,
                                                     unsigned long long b,
                                                     unsigned long long c) {
    unsigned long long d;
    asm("fma.rn.f32x2 %0, %1, %2, %3;" : "=l"(d) : "l"(a), "l"(b), "l"(c));
    return d;
}
__device__ __forceinline__ unsigned long long f2_mul(unsigned long long a,
                                                     unsigned long long b) {
    unsigned long long d;
    asm("mul.rn.f32x2 %0, %1, %2;" : "=l"(d) : "l"(a), "l"(b));
    return d;
}

extern __shared__ float nmu_smem[];

__global__ void __launch_bounds__(256, 3)
nmu_kernel(const float* __restrict__ x, const float* __restrict__ M,
           float* __restrict__ out) {
    float* xs = nmu_smem;                        // [NMU_BROWS][NMU_D]  (x - 1)
    float* ms = nmu_smem + NMU_BROWS * NMU_D;    // [NMU_O][NMU_MSTRIDE] clipped M^T

    const int tid = threadIdx.x;
    const int b0  = blockIdx.x * NMU_BROWS;

    // ---- Stage M_hat transposed: ms[o][d] = saturate(M[d][o]) ----
    #pragma unroll
    for (int i = tid; i < NMU_D * NMU_O; i += 256) {
        int d = i >> 5;          // row of M
        int o = i & 31;          // col of M
        ms[o * NMU_MSTRIDE + d] = __saturatef(M[i]);
    }

    // ---- Stage x tile as (x - 1), vectorized ----
    const float4* __restrict__ xg = (const float4*)(x + (size_t)b0 * NMU_D);
    float4* xs4 = (float4*)xs;
    #pragma unroll
    for (int i = 0; i < (NMU_BROWS * NMU_D / 4) / 256; i++) {  // 8 iters
        int idx = tid + i * 256;
        float4 v = xg[idx];
        v.x -= 1.0f; v.y -= 1.0f; v.z -= 1.0f; v.w -= 1.0f;
        xs4[idx] = v;
    }
    __syncthreads();

    const int warp = tid >> 5;
    const int o    = tid & 31;
    const unsigned long long* __restrict__ mrow =
        (const unsigned long long*)(ms + o * NMU_MSTRIDE);
    const float* __restrict__ xbase = xs + warp * NMU_RPW * NMU_D;

    const unsigned long long ONE2 = 0x3f8000003f800000ULL;  // (1.0f, 1.0f)
    unsigned long long p[NMU_RPW];
    #pragma unroll
    for (int r = 0; r < NMU_RPW; r++) p[r] = ONE2;

    // ---- Main loop: 8 d's per iteration ----
    #pragma unroll 4
    for (int d = 0; d < NMU_D; d += 8) {
        unsigned long long m0 = mrow[(d >> 1) + 0];
        unsigned long long m1 = mrow[(d >> 1) + 1];
        unsigned long long m2 = mrow[(d >> 1) + 2];
        unsigned long long m3 = mrow[(d >> 1) + 3];
        #pragma unroll
        for (int r = 0; r < NMU_RPW; r++) {
            const ulonglong2* xp =
                (const ulonglong2*)(xbase + r * NMU_D + d);
            ulonglong2 xa = xp[0];   // d+0..3  (x-1 pairs)
            ulonglong2 xb = xp[1];   // d+4..7
            unsigned long long t;
            t = f2_fma(m0, xa.x, ONE2); p[r] = f2_mul(p[r], t);
            t = f2_fma(m1, xa.y, ONE2); p[r] = f2_mul(p[r], t);
            t = f2_fma(m2, xb.x, ONE2); p[r] = f2_mul(p[r], t);
            t = f2_fma(m3, xb.y, ONE2); p[r] = f2_mul(p[r], t);
        }
    }

    // ---- Epilogue: combine even/odd partial products, coalesced store ----
    #pragma unroll
    for (int r = 0; r < NMU_RPW; r++) {
        float lo = __uint_as_float((unsigned)(p[r] & 0xffffffffULL));
        float hi = __uint_as_float((unsigned)(p[r] >> 32));
        int row = b0 + warp * NMU_RPW + r;
        out[(size_t)row * NMU_O + o] = lo * hi;
    }
}

extern "C" void kernel_launch(void* const* d_in, const int* in_sizes, int n_in,
                              void* d_out, int out_size) {
    const float* x = (const float*)d_in[0];   // [16384, 256]
    const float* M = (const float*)d_in[1];   // [256, 32]
    float* out = (float*)d_out;               // [16384, 32]

    const int B = in_sizes[0] / NMU_D;        // 16384
    const size_t smem_bytes =
        (size_t)(NMU_BROWS * NMU_D + NMU_O * NMU_MSTRIDE) * sizeof(float); // 65792

    cudaFuncSetAttribute(nmu_kernel,
                         cudaFuncAttributeMaxDynamicSharedMemorySize,
                         (int)smem_bytes);

    dim3 grid(B / NMU_BROWS);                 // 512
    dim3 block(256);
    nmu_kernel<<<grid, block, smem_bytes>>>(x, M, out);
}